// round 8
// baseline (speedup 1.0000x reference)
#include <cuda_runtime.h>
#include <cuda_fp16.h>
#include <cstdint>
#include <cstddef>

#define DEV __device__ __forceinline__

static constexpr int BD = 4096, HD = 1024, KD = 2048, ND = 4096;
static constexpr int TM = 128, TN = 128, KC = 64;
static constexpr int NKC = KD / KC;                  // 32 chunks
static constexpr int NSTG = 4;
static constexpr int STG_A = TM * KC * 2;            // 16384
static constexpr int STG_B = TN * KC * 2;            // 16384
static constexpr int STG_BYTES = STG_A + STG_B;      // 32768
static constexpr int SM_BIAS = NSTG * STG_BYTES;     // 131072
static constexpr int SMEM_TOTAL = SM_BIAS + 128 * 4;

__device__ __align__(16) __half g_Apk[(size_t)BD * KD];   // frag-ordered
__device__ __align__(16) __half g_Bpk[(size_t)ND * KD];   // frag-ordered + gate-interleaved

DEV uint32_t smem_u32(const void* p) {
    uint32_t a;
    asm("{ .reg .u64 t; cvta.to.shared.u64 t, %1; cvt.u32.u64 %0, t; }" : "=r"(a) : "l"(p));
    return a;
}
DEV void cpa16(uint32_t d, const void* s) {
    asm volatile("cp.async.cg.shared.global [%0], [%1], 16;" :: "r"(d), "l"(s) : "memory");
}
DEV void cpa_commit() { asm volatile("cp.async.commit_group;" ::: "memory"); }
template <int N> DEV void cpa_wait() { asm volatile("cp.async.wait_group %0;" :: "n"(N) : "memory"); }

DEV float sigf(float x)  { return 1.0f / (1.0f + __expf(-x)); }
DEV float tanhf_(float x) {
    float e = __expf(-2.0f * fabsf(x));
    return copysignf((1.0f - e) / (1.0f + e), x);
}

#define LDS128(v, a) asm volatile("ld.shared.v4.b32 {%0,%1,%2,%3}, [%4];" \
    : "=r"((v)[0]), "=r"((v)[1]), "=r"((v)[2]), "=r"((v)[3]) : "r"(a))
#define LDS64(v, a) asm volatile("ld.shared.v2.b32 {%0,%1}, [%2];" \
    : "=r"((v)[0]), "=r"((v)[1]) : "r"(a))
#define MMA16(c, a, b) asm volatile( \
    "mma.sync.aligned.m16n8k16.row.col.f32.f16.f16.f32 " \
    "{%0,%1,%2,%3}, {%4,%5,%6,%7}, {%8,%9}, {%0,%1,%2,%3};" \
    : "+f"((c)[0]), "+f"((c)[1]), "+f"((c)[2]), "+f"((c)[3]) \
    : "r"((a)[0]), "r"((a)[1]), "r"((a)[2]), "r"((a)[3]), "r"((b)[0]), "r"((b)[1]))

// ---- pack A: fp16 fragments of [x|h] (validated R4) ----
__global__ void __launch_bounds__(256) pack_a(const float* __restrict__ x,
                                              const float* __restrict__ h) {
    __shared__ float s[16][132];
    const int mb = blockIdx.x >> 4, kb = blockIdx.x & 15;
    const int t = threadIdx.x;
    const float* base = (kb < 8) ? x + (size_t)mb * 16 * 1024 + kb * 128
                                 : h + (size_t)mb * 16 * 1024 + (kb - 8) * 128;
#pragma unroll
    for (int i = 0; i < 2; ++i) {
        int q = t + i * 256;
        int row = q >> 5, c4 = q & 31;
        float4 v = *(const float4*)(base + (size_t)row * 1024 + c4 * 4);
        s[row][c4 * 4 + 0] = v.x; s[row][c4 * 4 + 1] = v.y;
        s[row][c4 * 4 + 2] = v.z; s[row][c4 * 4 + 3] = v.w;
    }
    __syncthreads();
    const int j = t >> 5, lane = t & 31;
    __half2 hv[4];
#pragma unroll
    for (int slot = 0; slot < 4; ++slot) {
        int r = (lane >> 2) + (slot & 1) * 8;
        int c = (lane & 3) * 2 + (slot & 2) * 4;
        hv[slot] = __floats2half2_rn(s[r][j * 16 + c], s[r][j * 16 + c + 1]);
    }
    size_t idx = ((size_t)(mb * 128 + kb * 8 + j) * 32 + lane) * 8;
    *(uint4*)(g_Apk + idx) = *(uint4*)hv;
}

// ---- pack B: fp16 fragments, gate-interleaved (validated R4) ----
__global__ void __launch_bounds__(256) pack_b(const float* __restrict__ wi,
                                              const float* __restrict__ wh) {
    __shared__ float s[64][36];
    const int b = blockIdx.x;
    const int kb = b & 31, tt = (b >> 5) & 31, gate = b >> 10;
    const int n0 = gate * 1024 + tt * 32, k0 = kb * 64;
    const int t = threadIdx.x;
#pragma unroll
    for (int i = 0; i < 2; ++i) {
        int q = t + i * 256;
        int kr = q >> 3, c4 = q & 7;
        int k = k0 + kr;
        const float* src = ((k < HD) ? wi + (size_t)k * ND : wh + (size_t)(k - HD) * ND) + n0;
        float4 v = *(const float4*)(src + c4 * 4);
        s[kr][c4 * 4 + 0] = v.x; s[kr][c4 * 4 + 1] = v.y;
        s[kr][c4 * 4 + 2] = v.z; s[kr][c4 * 4 + 3] = v.w;
    }
    __syncthreads();
#pragma unroll
    for (int i = 0; i < 2; ++i) {
        int u = t + i * 256;
        int w = u >> 7, k16 = (u >> 5) & 3, lane = u & 31;
        int nl = w * 8 + (lane >> 2);
        int kk = k16 * 16 + (lane & 3) * 2;
        __half2 p[2];
        p[0] = __floats2half2_rn(s[kk][nl], s[kk + 1][nl]);
        p[1] = __floats2half2_rn(s[kk + 8][nl], s[kk + 9][nl]);
        int nbp = tt * 16 + w * 4 + gate;
        size_t idx = ((size_t)(nbp * 128 + kb * 4 + k16) * 32 + lane) * 4;
        *(uint2*)(g_Bpk + idx) = *(uint2*)p;
    }
}

// ---- fused fp16 GEMM (128x128 tile, 256 thr) + LSTM epilogue ----
__global__ void __launch_bounds__(256, 1) gemm_lstm(const float* __restrict__ c_t,
                                                    const float* __restrict__ b_i,
                                                    const float* __restrict__ b_h,
                                                    float* __restrict__ out) {
    extern __shared__ char smem[];
    const uint32_t sb = smem_u32(smem);
    float* bias_s = (float*)(smem + SM_BIAS);
    const int tid = threadIdx.x, wid = tid >> 5, lane = tid & 31;
    const int wm = wid >> 2, wn = wid & 3;         // 2 x 4 warp grid, warp tile 64x32
    const int m0 = blockIdx.y * TM;
    const int bx = blockIdx.x;
    const int mb0 = blockIdx.y * 8, nb0 = bx * 16;

    if (tid < 128) {
        int gate = tid >> 5, hl = tid & 31, col = gate * 1024 + bx * 32 + hl;
        bias_s[tid] = b_i[col] + b_h[col];
    }

    float acc[4][4][4];
#pragma unroll
    for (int i = 0; i < 4; ++i)
#pragma unroll
        for (int j = 0; j < 4; ++j)
#pragma unroll
            for (int u = 0; u < 4; ++u) acc[i][j][u] = 0.f;

    auto issue = [&](int s, int kc) {
        const uint32_t SA = sb + s * STG_BYTES, SB = SA + STG_A;
        // A: 1024 x 16B
#pragma unroll
        for (int i = 0; i < 4; ++i) {
            int u = tid + i * 256;
            int mb = u >> 7, j = (u >> 5) & 3, ln = u & 31;
            cpa16(SA + u * 16,
                  g_Apk + ((size_t)((mb0 + mb) * 128 + kc * 4 + j) * 32 + ln) * 8);
        }
        // B: 1024 x 16B
#pragma unroll
        for (int i = 0; i < 4; ++i) {
            int u = tid + i * 256;
            int nb = u >> 6, j = (u >> 4) & 3, q = u & 15;
            cpa16(SB + u * 16,
                  g_Bpk + ((size_t)((nb0 + nb) * 128 + kc * 4 + j) * 32) * 4 + q * 8);
        }
        cpa_commit();
    };

    issue(0, 0);
    issue(1, 1);
    issue(2, 2);

    for (int kc = 0; kc < NKC; ++kc) {
        const int s = kc & (NSTG - 1);
        cpa_wait<2>();
        __syncthreads();
        if (kc + 3 < NKC) issue((kc + 3) & (NSTG - 1), kc + 3);
        else cpa_commit();
        const uint32_t SA = sb + s * STG_BYTES, SB = SA + STG_A;
#pragma unroll
        for (int j = 0; j < 4; ++j) {
            uint32_t a[4][4], b[4][2];
#pragma unroll
            for (int im = 0; im < 4; ++im)
                LDS128(a[im], SA + (((wm * 4 + im) * 4 + j) * 32 + lane) * 16);
#pragma unroll
            for (int in = 0; in < 4; ++in)
                LDS64(b[in], SB + (((wn * 4 + in) * 4 + j) * 32 + lane) * 8);
#pragma unroll
            for (int im = 0; im < 4; ++im)
#pragma unroll
                for (int in = 0; in < 4; ++in)
                    MMA16(acc[im][in], a[im], b[in]);
        }
    }

    // ---- fused epilogue: in-index = gate ----
    const int hl = wn * 8 + (lane & 3) * 2;
    const int hc = bx * 32 + hl;
    const int rb = m0 + wm * 64 + (lane >> 2);
    float bI0 = bias_s[hl],      bI1 = bias_s[hl + 1];
    float bF0 = bias_s[32 + hl], bF1 = bias_s[33 + hl];
    float bG0 = bias_s[64 + hl], bG1 = bias_s[65 + hl];
    float bO0 = bias_s[96 + hl], bO1 = bias_s[97 + hl];
#pragma unroll
    for (int im = 0; im < 4; ++im)
#pragma unroll
        for (int half = 0; half < 2; ++half) {
            const int r = rb + im * 16 + half * 8;
            const int q = half * 2;
            float2 cv = *(const float2*)(c_t + (size_t)r * HD + hc);
            float I0 = sigf(acc[im][0][q] + bI0),   I1 = sigf(acc[im][0][q + 1] + bI1);
            float F0 = sigf(acc[im][1][q] + bF0),   F1 = sigf(acc[im][1][q + 1] + bF1);
            float G0 = tanhf_(acc[im][2][q] + bG0), G1 = tanhf_(acc[im][2][q + 1] + bG1);
            float O0 = sigf(acc[im][3][q] + bO0),   O1 = sigf(acc[im][3][q + 1] + bO1);
            float cn0 = F0 * cv.x + I0 * G0,        cn1 = F1 * cv.y + I1 * G1;
            float hn0 = O0 * tanhf_(cn0),           hn1 = O1 * tanhf_(cn1);
            *(float2*)(out + (size_t)r * HD + hc) = make_float2(hn0, hn1);
            *(float2*)(out + (size_t)BD * HD + (size_t)r * HD + hc) = make_float2(cn0, cn1);
        }
}

extern "C" void kernel_launch(void* const* d_in, const int* in_sizes, int n_in,
                              void* d_out, int out_size) {
    const float* input = (const float*)d_in[0];
    const float* h_t   = (const float*)d_in[1];
    const float* c_t   = (const float*)d_in[2];
    const float* w_i   = (const float*)d_in[3];
    const float* w_h   = (const float*)d_in[4];
    const float* b_i   = (const float*)d_in[5];
    const float* b_h   = (const float*)d_in[6];
    float* out = (float*)d_out;

    cudaFuncSetAttribute(gemm_lstm, cudaFuncAttributeMaxDynamicSharedMemorySize, SMEM_TOTAL);

    pack_a<<<256 * 16, 256>>>(input, h_t);
    pack_b<<<4 * 32 * 32, 256>>>(w_i, w_h);
    gemm_lstm<<<dim3(ND / TN, BD / TM), 256, SMEM_TOTAL>>>(c_t, b_i, b_h, out);
}

// round 9
// speedup vs baseline: 1.2175x; 1.2175x over previous
#include <cuda_runtime.h>
#include <cuda_fp16.h>
#include <cstdint>
#include <cstddef>

#define DEV __device__ __forceinline__

static constexpr int BD = 4096, HD = 1024, KD = 2048, ND = 4096;
static constexpr int TM = 128, TN = 128, KC = 64;
static constexpr int NKC = KD / KC;                  // 32 chunks
static constexpr int NSTG = 3;
static constexpr int STG_A = TM * KC * 2;            // 16384
static constexpr int STG_B = TN * KC * 2;            // 16384
static constexpr int STG_BYTES = STG_A + STG_B;      // 32768
static constexpr int SM_BIAS = NSTG * STG_BYTES;     // 98304
static constexpr int SMEM_TOTAL = SM_BIAS + 128 * 4; // 98816 (<114KB -> 2 CTAs/SM)

__device__ __align__(16) __half g_Apk[(size_t)BD * KD];   // frag-ordered
__device__ __align__(16) __half g_Bpk[(size_t)ND * KD];   // frag-ordered + gate-interleaved

DEV uint32_t smem_u32(const void* p) {
    uint32_t a;
    asm("{ .reg .u64 t; cvta.to.shared.u64 t, %1; cvt.u32.u64 %0, t; }" : "=r"(a) : "l"(p));
    return a;
}
DEV void cpa16(uint32_t d, const void* s) {
    asm volatile("cp.async.cg.shared.global [%0], [%1], 16;" :: "r"(d), "l"(s) : "memory");
}
DEV void cpa_commit() { asm volatile("cp.async.commit_group;" ::: "memory"); }
template <int N> DEV void cpa_wait() { asm volatile("cp.async.wait_group %0;" :: "n"(N) : "memory"); }

DEV float sigf(float x)  { return 1.0f / (1.0f + __expf(-x)); }
DEV float tanhf_(float x) {
    float e = __expf(-2.0f * fabsf(x));
    return copysignf((1.0f - e) / (1.0f + e), x);
}

#define LDS128(v, a) asm volatile("ld.shared.v4.b32 {%0,%1,%2,%3}, [%4];" \
    : "=r"((v)[0]), "=r"((v)[1]), "=r"((v)[2]), "=r"((v)[3]) : "r"(a))
#define LDS64(v, a) asm volatile("ld.shared.v2.b32 {%0,%1}, [%2];" \
    : "=r"((v)[0]), "=r"((v)[1]) : "r"(a))
#define MMA16(c, a, b) asm volatile( \
    "mma.sync.aligned.m16n8k16.row.col.f32.f16.f16.f32 " \
    "{%0,%1,%2,%3}, {%4,%5,%6,%7}, {%8,%9}, {%0,%1,%2,%3};" \
    : "+f"((c)[0]), "+f"((c)[1]), "+f"((c)[2]), "+f"((c)[3]) \
    : "r"((a)[0]), "r"((a)[1]), "r"((a)[2]), "r"((a)[3]), "r"((b)[0]), "r"((b)[1]))

// ---- pack A: fp16 fragments of [x|h] (validated R4) ----
__global__ void __launch_bounds__(256) pack_a(const float* __restrict__ x,
                                              const float* __restrict__ h) {
    __shared__ float s[16][132];
    const int mb = blockIdx.x >> 4, kb = blockIdx.x & 15;
    const int t = threadIdx.x;
    const float* base = (kb < 8) ? x + (size_t)mb * 16 * 1024 + kb * 128
                                 : h + (size_t)mb * 16 * 1024 + (kb - 8) * 128;
#pragma unroll
    for (int i = 0; i < 2; ++i) {
        int q = t + i * 256;
        int row = q >> 5, c4 = q & 31;
        float4 v = *(const float4*)(base + (size_t)row * 1024 + c4 * 4);
        s[row][c4 * 4 + 0] = v.x; s[row][c4 * 4 + 1] = v.y;
        s[row][c4 * 4 + 2] = v.z; s[row][c4 * 4 + 3] = v.w;
    }
    __syncthreads();
    const int j = t >> 5, lane = t & 31;
    __half2 hv[4];
#pragma unroll
    for (int slot = 0; slot < 4; ++slot) {
        int r = (lane >> 2) + (slot & 1) * 8;
        int c = (lane & 3) * 2 + (slot & 2) * 4;
        hv[slot] = __floats2half2_rn(s[r][j * 16 + c], s[r][j * 16 + c + 1]);
    }
    size_t idx = ((size_t)(mb * 128 + kb * 8 + j) * 32 + lane) * 8;
    *(uint4*)(g_Apk + idx) = *(uint4*)hv;
}

// ---- pack B: fp16 fragments, gate-interleaved (validated R4) ----
__global__ void __launch_bounds__(256) pack_b(const float* __restrict__ wi,
                                              const float* __restrict__ wh) {
    __shared__ float s[64][36];
    const int b = blockIdx.x;
    const int kb = b & 31, tt = (b >> 5) & 31, gate = b >> 10;
    const int n0 = gate * 1024 + tt * 32, k0 = kb * 64;
    const int t = threadIdx.x;
#pragma unroll
    for (int i = 0; i < 2; ++i) {
        int q = t + i * 256;
        int kr = q >> 3, c4 = q & 7;
        int k = k0 + kr;
        const float* src = ((k < HD) ? wi + (size_t)k * ND : wh + (size_t)(k - HD) * ND) + n0;
        float4 v = *(const float4*)(src + c4 * 4);
        s[kr][c4 * 4 + 0] = v.x; s[kr][c4 * 4 + 1] = v.y;
        s[kr][c4 * 4 + 2] = v.z; s[kr][c4 * 4 + 3] = v.w;
    }
    __syncthreads();
#pragma unroll
    for (int i = 0; i < 2; ++i) {
        int u = t + i * 256;
        int w = u >> 7, k16 = (u >> 5) & 3, lane = u & 31;
        int nl = w * 8 + (lane >> 2);
        int kk = k16 * 16 + (lane & 3) * 2;
        __half2 p[2];
        p[0] = __floats2half2_rn(s[kk][nl], s[kk + 1][nl]);
        p[1] = __floats2half2_rn(s[kk + 8][nl], s[kk + 9][nl]);
        int nbp = tt * 16 + w * 4 + gate;
        size_t idx = ((size_t)(nbp * 128 + kb * 4 + k16) * 32 + lane) * 4;
        *(uint2*)(g_Bpk + idx) = *(uint2*)p;
    }
}

// ---- fused fp16 GEMM (128x128 tile, 256 thr, 2 CTAs/SM) + LSTM epilogue ----
__global__ void __launch_bounds__(256, 2) gemm_lstm(const float* __restrict__ c_t,
                                                    const float* __restrict__ b_i,
                                                    const float* __restrict__ b_h,
                                                    float* __restrict__ out) {
    extern __shared__ char smem[];
    const uint32_t sb = smem_u32(smem);
    float* bias_s = (float*)(smem + SM_BIAS);
    const int tid = threadIdx.x, wid = tid >> 5, lane = tid & 31;
    const int wm = wid >> 2, wn = wid & 3;         // 2 x 4 warp grid, warp tile 64x32
    const int m0 = blockIdx.y * TM;
    const int bx = blockIdx.x;
    const int mb0 = blockIdx.y * 8, nb0 = bx * 16;

    if (tid < 128) {
        int gate = tid >> 5, hl = tid & 31, col = gate * 1024 + bx * 32 + hl;
        bias_s[tid] = b_i[col] + b_h[col];
    }

    float acc[4][4][4];
#pragma unroll
    for (int i = 0; i < 4; ++i)
#pragma unroll
        for (int j = 0; j < 4; ++j)
#pragma unroll
            for (int u = 0; u < 4; ++u) acc[i][j][u] = 0.f;

    auto issue = [&](int s, int kc) {
        const uint32_t SA = sb + s * STG_BYTES, SB = SA + STG_A;
        // A: 1024 x 16B
#pragma unroll
        for (int i = 0; i < 4; ++i) {
            int u = tid + i * 256;
            int mb = u >> 7, j = (u >> 5) & 3, ln = u & 31;
            cpa16(SA + u * 16,
                  g_Apk + ((size_t)((mb0 + mb) * 128 + kc * 4 + j) * 32 + ln) * 8);
        }
        // B: 1024 x 16B
#pragma unroll
        for (int i = 0; i < 4; ++i) {
            int u = tid + i * 256;
            int nb = u >> 6, j = (u >> 4) & 3, q = u & 15;
            cpa16(SB + u * 16,
                  g_Bpk + ((size_t)((nb0 + nb) * 128 + kc * 4 + j) * 32) * 4 + q * 8);
        }
        cpa_commit();
    };

    issue(0, 0);
    issue(1, 1);

    for (int kc = 0; kc < NKC; ++kc) {
        const int s = kc % NSTG;
        cpa_wait<1>();
        __syncthreads();
        if (kc + 2 < NKC) issue((kc + 2) % NSTG, kc + 2);
        else cpa_commit();               // keep group count for wait<1>
        const uint32_t SA = sb + s * STG_BYTES, SB = SA + STG_A;
#pragma unroll
        for (int j = 0; j < 4; ++j) {
            uint32_t a[4][4], b[4][2];
#pragma unroll
            for (int im = 0; im < 4; ++im)
                LDS128(a[im], SA + (((wm * 4 + im) * 4 + j) * 32 + lane) * 16);
#pragma unroll
            for (int in = 0; in < 4; ++in)
                LDS64(b[in], SB + (((wn * 4 + in) * 4 + j) * 32 + lane) * 8);
#pragma unroll
            for (int im = 0; im < 4; ++im)
#pragma unroll
                for (int in = 0; in < 4; ++in)
                    MMA16(acc[im][in], a[im], b[in]);
        }
    }

    // ---- fused epilogue: in-index = gate ----
    const int hl = wn * 8 + (lane & 3) * 2;
    const int hc = bx * 32 + hl;
    const int rb = m0 + wm * 64 + (lane >> 2);
    float bI0 = bias_s[hl],      bI1 = bias_s[hl + 1];
    float bF0 = bias_s[32 + hl], bF1 = bias_s[33 + hl];
    float bG0 = bias_s[64 + hl], bG1 = bias_s[65 + hl];
    float bO0 = bias_s[96 + hl], bO1 = bias_s[97 + hl];
#pragma unroll
    for (int im = 0; im < 4; ++im)
#pragma unroll
        for (int half = 0; half < 2; ++half) {
            const int r = rb + im * 16 + half * 8;
            const int q = half * 2;
            float2 cv = *(const float2*)(c_t + (size_t)r * HD + hc);
            float I0 = sigf(acc[im][0][q] + bI0),   I1 = sigf(acc[im][0][q + 1] + bI1);
            float F0 = sigf(acc[im][1][q] + bF0),   F1 = sigf(acc[im][1][q + 1] + bF1);
            float G0 = tanhf_(acc[im][2][q] + bG0), G1 = tanhf_(acc[im][2][q + 1] + bG1);
            float O0 = sigf(acc[im][3][q] + bO0),   O1 = sigf(acc[im][3][q + 1] + bO1);
            float cn0 = F0 * cv.x + I0 * G0,        cn1 = F1 * cv.y + I1 * G1;
            float hn0 = O0 * tanhf_(cn0),           hn1 = O1 * tanhf_(cn1);
            *(float2*)(out + (size_t)r * HD + hc) = make_float2(hn0, hn1);
            *(float2*)(out + (size_t)BD * HD + (size_t)r * HD + hc) = make_float2(cn0, cn1);
        }
}

extern "C" void kernel_launch(void* const* d_in, const int* in_sizes, int n_in,
                              void* d_out, int out_size) {
    const float* input = (const float*)d_in[0];
    const float* h_t   = (const float*)d_in[1];
    const float* c_t   = (const float*)d_in[2];
    const float* w_i   = (const float*)d_in[3];
    const float* w_h   = (const float*)d_in[4];
    const float* b_i   = (const float*)d_in[5];
    const float* b_h   = (const float*)d_in[6];
    float* out = (float*)d_out;

    cudaFuncSetAttribute(gemm_lstm, cudaFuncAttributeMaxDynamicSharedMemorySize, SMEM_TOTAL);

    pack_a<<<256 * 16, 256>>>(input, h_t);
    pack_b<<<4 * 32 * 32, 256>>>(w_i, w_h);
    gemm_lstm<<<dim3(ND / TN, BD / TM), 256, SMEM_TOTAL>>>(c_t, b_i, b_h, out);
}

// round 10
// speedup vs baseline: 1.2319x; 1.0118x over previous
#include <cuda_runtime.h>
#include <cuda_fp16.h>
#include <cstdint>
#include <cstddef>

#define DEV __device__ __forceinline__

static constexpr int BD = 4096, HD = 1024, KD = 2048, ND = 4096;
static constexpr int TM = 128, TN = 128, KC = 64;
static constexpr int NKC = KD / KC;                  // 32 chunks
static constexpr int NSTG = 3;
static constexpr int STG_A = TM * KC * 2;            // 16384
static constexpr int STG_B = TN * KC * 2;            // 16384
static constexpr int STG_BYTES = STG_A + STG_B;      // 32768
static constexpr int SM_BIAS = NSTG * STG_BYTES;     // 98304
static constexpr int SMEM_TOTAL = SM_BIAS + 128 * 4; // 98816 (2 CTAs/SM)

__device__ __align__(16) __half g_Apk[(size_t)BD * KD];   // frag-ordered
__device__ __align__(16) __half g_Bpk[(size_t)ND * KD];   // frag-ordered + gate-interleaved

DEV uint32_t smem_u32(const void* p) {
    uint32_t a;
    asm("{ .reg .u64 t; cvta.to.shared.u64 t, %1; cvt.u32.u64 %0, t; }" : "=r"(a) : "l"(p));
    return a;
}
DEV void cpa16(uint32_t d, const void* s) {
    asm volatile("cp.async.cg.shared.global [%0], [%1], 16;" :: "r"(d), "l"(s) : "memory");
}
DEV void cpa_commit() { asm volatile("cp.async.commit_group;" ::: "memory"); }
template <int N> DEV void cpa_wait() { asm volatile("cp.async.wait_group %0;" :: "n"(N) : "memory"); }

DEV float sigf(float x)  { return 1.0f / (1.0f + __expf(-x)); }
DEV float tanhf_(float x) {
    float e = __expf(-2.0f * fabsf(x));
    return copysignf((1.0f - e) / (1.0f + e), x);
}

#define LDS128(v, a) asm volatile("ld.shared.v4.b32 {%0,%1,%2,%3}, [%4];" \
    : "=r"((v)[0]), "=r"((v)[1]), "=r"((v)[2]), "=r"((v)[3]) : "r"(a))
#define LDS64(v, a) asm volatile("ld.shared.v2.b32 {%0,%1}, [%2];" \
    : "=r"((v)[0]), "=r"((v)[1]) : "r"(a))
#define MMA16(c, a, b) asm volatile( \
    "mma.sync.aligned.m16n8k16.row.col.f32.f16.f16.f32 " \
    "{%0,%1,%2,%3}, {%4,%5,%6,%7}, {%8,%9}, {%0,%1,%2,%3};" \
    : "+f"((c)[0]), "+f"((c)[1]), "+f"((c)[2]), "+f"((c)[3]) \
    : "r"((a)[0]), "r"((a)[1]), "r"((a)[2]), "r"((a)[3]), "r"((b)[0]), "r"((b)[1]))

// ---- merged pack A + pack B (bodies identical to validated R4 kernels) ----
// blocks [0, 4096): pack A tiles;  blocks [4096, 8192): pack B tiles.
__global__ void __launch_bounds__(256) pack_ab(const float* __restrict__ x,
                                               const float* __restrict__ h,
                                               const float* __restrict__ wi,
                                               const float* __restrict__ wh) {
    __shared__ float sm[2304];                 // max(16*132, 64*36) floats
    const int t = threadIdx.x;
    if (blockIdx.x < 4096) {
        float (*s)[132] = (float(*)[132])sm;
        const int mb = blockIdx.x >> 4, kb = blockIdx.x & 15;
        const float* base = (kb < 8) ? x + (size_t)mb * 16 * 1024 + kb * 128
                                     : h + (size_t)mb * 16 * 1024 + (kb - 8) * 128;
#pragma unroll
        for (int i = 0; i < 2; ++i) {
            int q = t + i * 256;
            int row = q >> 5, c4 = q & 31;
            float4 v = *(const float4*)(base + (size_t)row * 1024 + c4 * 4);
            s[row][c4 * 4 + 0] = v.x; s[row][c4 * 4 + 1] = v.y;
            s[row][c4 * 4 + 2] = v.z; s[row][c4 * 4 + 3] = v.w;
        }
        __syncthreads();
        const int j = t >> 5, lane = t & 31;
        __half2 hv[4];
#pragma unroll
        for (int slot = 0; slot < 4; ++slot) {
            int r = (lane >> 2) + (slot & 1) * 8;
            int c = (lane & 3) * 2 + (slot & 2) * 4;
            hv[slot] = __floats2half2_rn(s[r][j * 16 + c], s[r][j * 16 + c + 1]);
        }
        size_t idx = ((size_t)(mb * 128 + kb * 8 + j) * 32 + lane) * 8;
        *(uint4*)(g_Apk + idx) = *(uint4*)hv;
    } else {
        float (*s)[36] = (float(*)[36])sm;
        const int b = blockIdx.x - 4096;
        const int kb = b & 31, tt = (b >> 5) & 31, gate = b >> 10;
        const int n0 = gate * 1024 + tt * 32, k0 = kb * 64;
#pragma unroll
        for (int i = 0; i < 2; ++i) {
            int q = t + i * 256;
            int kr = q >> 3, c4 = q & 7;
            int k = k0 + kr;
            const float* src = ((k < HD) ? wi + (size_t)k * ND : wh + (size_t)(k - HD) * ND) + n0;
            float4 v = *(const float4*)(src + c4 * 4);
            s[kr][c4 * 4 + 0] = v.x; s[kr][c4 * 4 + 1] = v.y;
            s[kr][c4 * 4 + 2] = v.z; s[kr][c4 * 4 + 3] = v.w;
        }
        __syncthreads();
#pragma unroll
        for (int i = 0; i < 2; ++i) {
            int u = t + i * 256;
            int w = u >> 7, k16 = (u >> 5) & 3, lane = u & 31;
            int nl = w * 8 + (lane >> 2);
            int kk = k16 * 16 + (lane & 3) * 2;
            __half2 p[2];
            p[0] = __floats2half2_rn(s[kk][nl], s[kk + 1][nl]);
            p[1] = __floats2half2_rn(s[kk + 8][nl], s[kk + 9][nl]);
            int nbp = tt * 16 + w * 4 + gate;
            size_t idx = ((size_t)(nbp * 128 + kb * 4 + k16) * 32 + lane) * 4;
            *(uint2*)(g_Bpk + idx) = *(uint2*)p;
        }
    }
}

// ---- fused fp16 GEMM (128x128 tile, 256 thr, 2 CTAs/SM) + LSTM epilogue ----
__global__ void __launch_bounds__(256, 2) gemm_lstm(const float* __restrict__ c_t,
                                                    const float* __restrict__ b_i,
                                                    const float* __restrict__ b_h,
                                                    float* __restrict__ out) {
    extern __shared__ char smem[];
    const uint32_t sb = smem_u32(smem);
    float* bias_s = (float*)(smem + SM_BIAS);
    const int tid = threadIdx.x, wid = tid >> 5, lane = tid & 31;
    const int wm = wid >> 2, wn = wid & 3;         // 2 x 4 warp grid, warp tile 64x32
    const int m0 = blockIdx.y * TM;
    const int bx = blockIdx.x;
    const int mb0 = blockIdx.y * 8, nb0 = bx * 16;

    float acc[4][4][4];
#pragma unroll
    for (int i = 0; i < 4; ++i)
#pragma unroll
        for (int j = 0; j < 4; ++j)
#pragma unroll
            for (int u = 0; u < 4; ++u) acc[i][j][u] = 0.f;

    auto issue = [&](int s, int kc) {
        const uint32_t SA = sb + s * STG_BYTES, SB = SA + STG_A;
        // A: 1024 x 16B
#pragma unroll
        for (int i = 0; i < 4; ++i) {
            int u = tid + i * 256;
            int mb = u >> 7, j = (u >> 5) & 3, ln = u & 31;
            cpa16(SA + u * 16,
                  g_Apk + ((size_t)((mb0 + mb) * 128 + kc * 4 + j) * 32 + ln) * 8);
        }
        // B: 1024 x 16B
#pragma unroll
        for (int i = 0; i < 4; ++i) {
            int u = tid + i * 256;
            int nb = u >> 6, j = (u >> 4) & 3, q = u & 15;
            cpa16(SB + u * 16,
                  g_Bpk + ((size_t)((nb0 + nb) * 128 + kc * 4 + j) * 32) * 4 + q * 8);
        }
        cpa_commit();
    };

    issue(0, 0);
    issue(1, 1);

    // bias after first prefetches so they aren't delayed behind these loads
    if (tid < 128) {
        int gate = tid >> 5, hl = tid & 31, col = gate * 1024 + bx * 32 + hl;
        bias_s[tid] = b_i[col] + b_h[col];
    }

    for (int kc = 0; kc < NKC; ++kc) {
        const int s = kc % NSTG;
        cpa_wait<1>();
        __syncthreads();
        if (kc + 2 < NKC) issue((kc + 2) % NSTG, kc + 2);
        else cpa_commit();               // keep group count for wait<1>
        const uint32_t SA = sb + s * STG_BYTES, SB = SA + STG_A;
#pragma unroll
        for (int j = 0; j < 4; ++j) {
            uint32_t a[4][4], b[4][2];
#pragma unroll
            for (int im = 0; im < 4; ++im)
                LDS128(a[im], SA + (((wm * 4 + im) * 4 + j) * 32 + lane) * 16);
#pragma unroll
            for (int in = 0; in < 4; ++in)
                LDS64(b[in], SB + (((wn * 4 + in) * 4 + j) * 32 + lane) * 8);
#pragma unroll
            for (int im = 0; im < 4; ++im)
#pragma unroll
                for (int in = 0; in < 4; ++in)
                    MMA16(acc[im][in], a[im], b[in]);
        }
    }

    // ---- fused epilogue: in-index = gate ----
    const int hl = wn * 8 + (lane & 3) * 2;
    const int hc = bx * 32 + hl;
    const int rb = m0 + wm * 64 + (lane >> 2);
    float bI0 = bias_s[hl],      bI1 = bias_s[hl + 1];
    float bF0 = bias_s[32 + hl], bF1 = bias_s[33 + hl];
    float bG0 = bias_s[64 + hl], bG1 = bias_s[65 + hl];
    float bO0 = bias_s[96 + hl], bO1 = bias_s[97 + hl];
#pragma unroll
    for (int im = 0; im < 4; ++im)
#pragma unroll
        for (int half = 0; half < 2; ++half) {
            const int r = rb + im * 16 + half * 8;
            const int q = half * 2;
            float2 cv = *(const float2*)(c_t + (size_t)r * HD + hc);
            float I0 = sigf(acc[im][0][q] + bI0),   I1 = sigf(acc[im][0][q + 1] + bI1);
            float F0 = sigf(acc[im][1][q] + bF0),   F1 = sigf(acc[im][1][q + 1] + bF1);
            float G0 = tanhf_(acc[im][2][q] + bG0), G1 = tanhf_(acc[im][2][q + 1] + bG1);
            float O0 = sigf(acc[im][3][q] + bO0),   O1 = sigf(acc[im][3][q + 1] + bO1);
            float cn0 = F0 * cv.x + I0 * G0,        cn1 = F1 * cv.y + I1 * G1;
            float hn0 = O0 * tanhf_(cn0),           hn1 = O1 * tanhf_(cn1);
            *(float2*)(out + (size_t)r * HD + hc) = make_float2(hn0, hn1);
            *(float2*)(out + (size_t)BD * HD + (size_t)r * HD + hc) = make_float2(cn0, cn1);
        }
}

extern "C" void kernel_launch(void* const* d_in, const int* in_sizes, int n_in,
                              void* d_out, int out_size) {
    const float* input = (const float*)d_in[0];
    const float* h_t   = (const float*)d_in[1];
    const float* c_t   = (const float*)d_in[2];
    const float* w_i   = (const float*)d_in[3];
    const float* w_h   = (const float*)d_in[4];
    const float* b_i   = (const float*)d_in[5];
    const float* b_h   = (const float*)d_in[6];
    float* out = (float*)d_out;

    cudaFuncSetAttribute(gemm_lstm, cudaFuncAttributeMaxDynamicSharedMemorySize, SMEM_TOTAL);

    pack_ab<<<8192, 256>>>(input, h_t, w_i, w_h);
    gemm_lstm<<<dim3(ND / TN, BD / TM), 256, SMEM_TOTAL>>>(c_t, b_i, b_h, out);
}

// round 11
// speedup vs baseline: 1.2900x; 1.0472x over previous
#include <cuda_runtime.h>
#include <cuda_fp16.h>
#include <cstdint>
#include <cstddef>

#define DEV __device__ __forceinline__

static constexpr int BD = 4096, HD = 1024, KD = 2048, ND = 4096;
static constexpr int TM = 128, TN = 128, KC = 64;
static constexpr int NKC = KD / KC;                  // 32 chunks
static constexpr int NSTG = 3;
static constexpr int STG_A = TM * KC * 2;            // 16384
static constexpr int STG_B = TN * KC * 2;            // 16384
static constexpr int STG_BYTES = STG_A + STG_B;      // 32768
static constexpr int SM_BIAS = NSTG * STG_BYTES;     // 98304
static constexpr int SMEM_TOTAL = SM_BIAS + 128 * 4; // 98816 (2 CTAs/SM)

__device__ __align__(16) __half g_Apk[(size_t)BD * KD];   // frag-ordered
__device__ __align__(16) __half g_Bpk[(size_t)ND * KD];   // frag-ordered + gate-interleaved

DEV uint32_t smem_u32(const void* p) {
    uint32_t a;
    asm("{ .reg .u64 t; cvta.to.shared.u64 t, %1; cvt.u32.u64 %0, t; }" : "=r"(a) : "l"(p));
    return a;
}
DEV void cpa16(uint32_t d, const void* s) {
    asm volatile("cp.async.cg.shared.global [%0], [%1], 16;" :: "r"(d), "l"(s) : "memory");
}
DEV void cpa_commit() { asm volatile("cp.async.commit_group;" ::: "memory"); }
template <int N> DEV void cpa_wait() { asm volatile("cp.async.wait_group %0;" :: "n"(N) : "memory"); }

DEV float sigf(float x)  { return 1.0f / (1.0f + __expf(-x)); }
DEV float tanhf_(float x) {
    float e = __expf(-2.0f * fabsf(x));
    return copysignf((1.0f - e) / (1.0f + e), x);
}

#define LDS128(v, a) asm volatile("ld.shared.v4.b32 {%0,%1,%2,%3}, [%4];" \
    : "=r"((v)[0]), "=r"((v)[1]), "=r"((v)[2]), "=r"((v)[3]) : "r"(a))
#define LDS64(v, a) asm volatile("ld.shared.v2.b32 {%0,%1}, [%2];" \
    : "=r"((v)[0]), "=r"((v)[1]) : "r"(a))
#define MMA16(c, a, b) asm volatile( \
    "mma.sync.aligned.m16n8k16.row.col.f32.f16.f16.f32 " \
    "{%0,%1,%2,%3}, {%4,%5,%6,%7}, {%8,%9}, {%0,%1,%2,%3};" \
    : "+f"((c)[0]), "+f"((c)[1]), "+f"((c)[2]), "+f"((c)[3]) \
    : "r"((a)[0]), "r"((a)[1]), "r"((a)[2]), "r"((a)[3]), "r"((b)[0]), "r"((b)[1]))

// ---- merged pack A + pack B (validated R9) ----
__global__ void __launch_bounds__(256) pack_ab(const float* __restrict__ x,
                                               const float* __restrict__ h,
                                               const float* __restrict__ wi,
                                               const float* __restrict__ wh) {
    __shared__ float sm[2304];
    const int t = threadIdx.x;
    if (blockIdx.x < 4096) {
        float (*s)[132] = (float(*)[132])sm;
        const int mb = blockIdx.x >> 4, kb = blockIdx.x & 15;
        const float* base = (kb < 8) ? x + (size_t)mb * 16 * 1024 + kb * 128
                                     : h + (size_t)mb * 16 * 1024 + (kb - 8) * 128;
#pragma unroll
        for (int i = 0; i < 2; ++i) {
            int q = t + i * 256;
            int row = q >> 5, c4 = q & 31;
            float4 v = *(const float4*)(base + (size_t)row * 1024 + c4 * 4);
            s[row][c4 * 4 + 0] = v.x; s[row][c4 * 4 + 1] = v.y;
            s[row][c4 * 4 + 2] = v.z; s[row][c4 * 4 + 3] = v.w;
        }
        __syncthreads();
        const int j = t >> 5, lane = t & 31;
        __half2 hv[4];
#pragma unroll
        for (int slot = 0; slot < 4; ++slot) {
            int r = (lane >> 2) + (slot & 1) * 8;
            int c = (lane & 3) * 2 + (slot & 2) * 4;
            hv[slot] = __floats2half2_rn(s[r][j * 16 + c], s[r][j * 16 + c + 1]);
        }
        size_t idx = ((size_t)(mb * 128 + kb * 8 + j) * 32 + lane) * 8;
        *(uint4*)(g_Apk + idx) = *(uint4*)hv;
    } else {
        float (*s)[36] = (float(*)[36])sm;
        const int b = blockIdx.x - 4096;
        const int kb = b & 31, tt = (b >> 5) & 31, gate = b >> 10;
        const int n0 = gate * 1024 + tt * 32, k0 = kb * 64;
#pragma unroll
        for (int i = 0; i < 2; ++i) {
            int q = t + i * 256;
            int kr = q >> 3, c4 = q & 7;
            int k = k0 + kr;
            const float* src = ((k < HD) ? wi + (size_t)k * ND : wh + (size_t)(k - HD) * ND) + n0;
            float4 v = *(const float4*)(src + c4 * 4);
            s[kr][c4 * 4 + 0] = v.x; s[kr][c4 * 4 + 1] = v.y;
            s[kr][c4 * 4 + 2] = v.z; s[kr][c4 * 4 + 3] = v.w;
        }
        __syncthreads();
#pragma unroll
        for (int i = 0; i < 2; ++i) {
            int u = t + i * 256;
            int w = u >> 7, k16 = (u >> 5) & 3, lane = u & 31;
            int nl = w * 8 + (lane >> 2);
            int kk = k16 * 16 + (lane & 3) * 2;
            __half2 p[2];
            p[0] = __floats2half2_rn(s[kk][nl], s[kk + 1][nl]);
            p[1] = __floats2half2_rn(s[kk + 8][nl], s[kk + 9][nl]);
            int nbp = tt * 16 + w * 4 + gate;
            size_t idx = ((size_t)(nbp * 128 + kb * 4 + k16) * 32 + lane) * 4;
            *(uint2*)(g_Bpk + idx) = *(uint2*)p;
        }
    }
}

// ---- fused fp16 GEMM (128x128 tile, 256 thr, 2 CTAs/SM) + LSTM epilogue ----
__global__ void __launch_bounds__(256, 2) gemm_lstm(const float* __restrict__ c_t,
                                                    const float* __restrict__ b_i,
                                                    const float* __restrict__ b_h,
                                                    float* __restrict__ out) {
    extern __shared__ char smem[];
    const uint32_t sb = smem_u32(smem);
    float* bias_s = (float*)(smem + SM_BIAS);
    const int tid = threadIdx.x, wid = tid >> 5, lane = tid & 31;
    const int wm = wid >> 2, wn = wid & 3;         // 2 x 4 warp grid, warp tile 64x32
    const int m0 = blockIdx.y * TM;
    const int bx = blockIdx.x;
    const int mb0 = blockIdx.y * 8, nb0 = bx * 16;

    float acc[4][4][4];
#pragma unroll
    for (int i = 0; i < 4; ++i)
#pragma unroll
        for (int j = 0; j < 4; ++j)
#pragma unroll
            for (int u = 0; u < 4; ++u) acc[i][j][u] = 0.f;

    auto issue = [&](int s, int kc) {
        const uint32_t SA = sb + s * STG_BYTES, SB = SA + STG_A;
#pragma unroll
        for (int i = 0; i < 4; ++i) {
            int u = tid + i * 256;
            int mb = u >> 7, j = (u >> 5) & 3, ln = u & 31;
            cpa16(SA + u * 16,
                  g_Apk + ((size_t)((mb0 + mb) * 128 + kc * 4 + j) * 32 + ln) * 8);
        }
#pragma unroll
        for (int i = 0; i < 4; ++i) {
            int u = tid + i * 256;
            int nb = u >> 6, j = (u >> 4) & 3, q = u & 15;
            cpa16(SB + u * 16,
                  g_Bpk + ((size_t)((nb0 + nb) * 128 + kc * 4 + j) * 32) * 4 + q * 8);
        }
        cpa_commit();
    };

    issue(0, 0);
    issue(1, 1);

    if (tid < 128) {
        int gate = tid >> 5, hl = tid & 31, col = gate * 1024 + bx * 32 + hl;
        bias_s[tid] = b_i[col] + b_h[col];
    }

    // per-warp fragment base offsets within a stage (addresses become base+imm)
    const uint32_t aoff = (uint32_t)(wm * 4) * 2048 + lane * 16;   // + im*2048 + j*512
    const uint32_t boff = STG_A + (uint32_t)(wn * 4) * 1024 + lane * 8; // + in*1024 + j*256

    for (int kc = 0; kc < NKC; ++kc) {
        const int s = kc % NSTG;
        cpa_wait<1>();
        __syncthreads();
        const uint32_t SA = sb + s * STG_BYTES;
        const uint32_t ab = SA + aoff, bb = SA + boff;

        uint32_t a[4][4], b[2][4][2];
        // j=0 fragments first (their latency is covered by the prefetch issue below)
#pragma unroll
        for (int im = 0; im < 4; ++im) LDS128(a[im], ab + im * 2048);
#pragma unroll
        for (int in = 0; in < 4; ++in) LDS64(b[0][in], bb + in * 1024);

        if (kc + 2 < NKC) issue((kc + 2) % NSTG, kc + 2);
        else cpa_commit();               // keep group count for wait<1>

#pragma unroll
        for (int j = 0; j < 4; ++j) {
            const int cur = j & 1;
            if (j < 3) {                 // B(j+1) into the other buffer, before MMAs
#pragma unroll
                for (int in = 0; in < 4; ++in)
                    LDS64(b[cur ^ 1][in], bb + in * 1024 + (j + 1) * 256);
            }
#pragma unroll
            for (int im = 0; im < 4; ++im)
#pragma unroll
                for (int in = 0; in < 4; ++in)
                    MMA16(acc[im][in], a[im], b[cur][in]);
            if (j < 3) {                 // A(j+1) after j's MMAs issued (WAR-safe in order)
#pragma unroll
                for (int im = 0; im < 4; ++im)
                    LDS128(a[im], ab + im * 2048 + (j + 1) * 512);
            }
        }
    }

    // ---- fused epilogue: in-index = gate ----
    const int hl = wn * 8 + (lane & 3) * 2;
    const int hc = bx * 32 + hl;
    const int rb = m0 + wm * 64 + (lane >> 2);
    float bI0 = bias_s[hl],      bI1 = bias_s[hl + 1];
    float bF0 = bias_s[32 + hl], bF1 = bias_s[33 + hl];
    float bG0 = bias_s[64 + hl], bG1 = bias_s[65 + hl];
    float bO0 = bias_s[96 + hl], bO1 = bias_s[97 + hl];
#pragma unroll
    for (int im = 0; im < 4; ++im)
#pragma unroll
        for (int half = 0; half < 2; ++half) {
            const int r = rb + im * 16 + half * 8;
            const int q = half * 2;
            float2 cv = *(const float2*)(c_t + (size_t)r * HD + hc);
            float I0 = sigf(acc[im][0][q] + bI0),   I1 = sigf(acc[im][0][q + 1] + bI1);
            float F0 = sigf(acc[im][1][q] + bF0),   F1 = sigf(acc[im][1][q + 1] + bF1);
            float G0 = tanhf_(acc[im][2][q] + bG0), G1 = tanhf_(acc[im][2][q + 1] + bG1);
            float O0 = sigf(acc[im][3][q] + bO0),   O1 = sigf(acc[im][3][q + 1] + bO1);
            float cn0 = F0 * cv.x + I0 * G0,        cn1 = F1 * cv.y + I1 * G1;
            float hn0 = O0 * tanhf_(cn0),           hn1 = O1 * tanhf_(cn1);
            *(float2*)(out + (size_t)r * HD + hc) = make_float2(hn0, hn1);
            *(float2*)(out + (size_t)BD * HD + (size_t)r * HD + hc) = make_float2(cn0, cn1);
        }
}

extern "C" void kernel_launch(void* const* d_in, const int* in_sizes, int n_in,
                              void* d_out, int out_size) {
    const float* input = (const float*)d_in[0];
    const float* h_t   = (const float*)d_in[1];
    const float* c_t   = (const float*)d_in[2];
    const float* w_i   = (const float*)d_in[3];
    const float* w_h   = (const float*)d_in[4];
    const float* b_i   = (const float*)d_in[5];
    const float* b_h   = (const float*)d_in[6];
    float* out = (float*)d_out;

    cudaFuncSetAttribute(gemm_lstm, cudaFuncAttributeMaxDynamicSharedMemorySize, SMEM_TOTAL);

    pack_ab<<<8192, 256>>>(input, h_t, w_i, w_h);
    gemm_lstm<<<dim3(ND / TN, BD / TM), 256, SMEM_TOTAL>>>(c_t, b_i, b_h, out);
}

// round 12
// speedup vs baseline: 1.2992x; 1.0071x over previous
#include <cuda_runtime.h>
#include <cuda_fp16.h>
#include <cstdint>
#include <cstddef>

#define DEV __device__ __forceinline__

static constexpr int BD = 4096, HD = 1024, KD = 2048, ND = 4096;
static constexpr int TM = 128, TN = 128, KC = 64;
static constexpr int NKC = KD / KC;                  // 32 chunks
static constexpr int NSTG = 3;
static constexpr int STG_A = TM * KC * 2;            // 16384
static constexpr int STG_B = TN * KC * 2;            // 16384
static constexpr int STG_BYTES = STG_A + STG_B;      // 32768
static constexpr int SM_BIAS = NSTG * STG_BYTES;     // 98304
static constexpr int SMEM_TOTAL = SM_BIAS + 128 * 4; // 98816 (2 CTAs/SM)

__device__ __align__(16) __half g_Apk[(size_t)BD * KD];   // frag-ordered
__device__ __align__(16) __half g_Bpk[(size_t)ND * KD];   // frag-ordered + gate-interleaved

DEV uint32_t smem_u32(const void* p) {
    uint32_t a;
    asm("{ .reg .u64 t; cvta.to.shared.u64 t, %1; cvt.u32.u64 %0, t; }" : "=r"(a) : "l"(p));
    return a;
}
DEV void cpa16(uint32_t d, const void* s) {
    asm volatile("cp.async.cg.shared.global [%0], [%1], 16;" :: "r"(d), "l"(s) : "memory");
}
DEV void cpa_commit() { asm volatile("cp.async.commit_group;" ::: "memory"); }
template <int N> DEV void cpa_wait() { asm volatile("cp.async.wait_group %0;" :: "n"(N) : "memory"); }

DEV float sigf(float x)  { return 1.0f / (1.0f + __expf(-x)); }
DEV float tanhf_(float x) {
    float e = __expf(-2.0f * fabsf(x));
    return copysignf((1.0f - e) / (1.0f + e), x);
}

#define LDS128(v, a) asm volatile("ld.shared.v4.b32 {%0,%1,%2,%3}, [%4];" \
    : "=r"((v)[0]), "=r"((v)[1]), "=r"((v)[2]), "=r"((v)[3]) : "r"(a))
#define LDS64(v, a) asm volatile("ld.shared.v2.b32 {%0,%1}, [%2];" \
    : "=r"((v)[0]), "=r"((v)[1]) : "r"(a))
#define MMA16(c, a, b) asm volatile( \
    "mma.sync.aligned.m16n8k16.row.col.f32.f16.f16.f32 " \
    "{%0,%1,%2,%3}, {%4,%5,%6,%7}, {%8,%9}, {%0,%1,%2,%3};" \
    : "+f"((c)[0]), "+f"((c)[1]), "+f"((c)[2]), "+f"((c)[3]) \
    : "r"((a)[0]), "r"((a)[1]), "r"((a)[2]), "r"((a)[3]), "r"((b)[0]), "r"((b)[1]))

// ---- merged pack A + pack B, 2 tiles per block for MLP=4 ----
// blocks [0, 2048): A tiles (mb, kb=2q, 2q+1);  [2048, 4096): B tiles (kb pairs)
__global__ void __launch_bounds__(256) pack_ab(const float* __restrict__ x,
                                               const float* __restrict__ h,
                                               const float* __restrict__ wi,
                                               const float* __restrict__ wh) {
    __shared__ float sm[4608];
    const int t = threadIdx.x;
    if (blockIdx.x < 2048) {
        const int mb = blockIdx.x >> 3, kp = (blockIdx.x & 7) * 2;
        float4 v[4];
#pragma unroll
        for (int t2 = 0; t2 < 2; ++t2) {
            const int kb = kp + t2;
            const float* base = (kb < 8) ? x + (size_t)mb * 16 * 1024 + kb * 128
                                         : h + (size_t)mb * 16 * 1024 + (kb - 8) * 128;
#pragma unroll
            for (int i = 0; i < 2; ++i) {
                int q = t + i * 256;
                v[t2 * 2 + i] = *(const float4*)(base + (size_t)(q >> 5) * 1024 + (q & 31) * 4);
            }
        }
#pragma unroll
        for (int t2 = 0; t2 < 2; ++t2) {
            float (*s)[132] = (float(*)[132])(sm + t2 * 2112);
#pragma unroll
            for (int i = 0; i < 2; ++i) {
                int q = t + i * 256;
                int row = q >> 5, c4 = q & 31;
                float4 w = v[t2 * 2 + i];
                s[row][c4 * 4 + 0] = w.x; s[row][c4 * 4 + 1] = w.y;
                s[row][c4 * 4 + 2] = w.z; s[row][c4 * 4 + 3] = w.w;
            }
        }
        __syncthreads();
        const int j = t >> 5, lane = t & 31;
#pragma unroll
        for (int t2 = 0; t2 < 2; ++t2) {
            float (*s)[132] = (float(*)[132])(sm + t2 * 2112);
            __half2 hv[4];
#pragma unroll
            for (int slot = 0; slot < 4; ++slot) {
                int r = (lane >> 2) + (slot & 1) * 8;
                int c = (lane & 3) * 2 + (slot & 2) * 4;
                hv[slot] = __floats2half2_rn(s[r][j * 16 + c], s[r][j * 16 + c + 1]);
            }
            size_t idx = ((size_t)(mb * 128 + (kp + t2) * 8 + j) * 32 + lane) * 8;
            *(uint4*)(g_Apk + idx) = *(uint4*)hv;
        }
    } else {
        const int b = blockIdx.x - 2048;
        const int kp = (b & 15) * 2, tt = (b >> 4) & 31, gate = b >> 9;
        const int n0 = gate * 1024 + tt * 32;
        float4 v[4];
#pragma unroll
        for (int t2 = 0; t2 < 2; ++t2) {
            const int k0 = (kp + t2) * 64;
#pragma unroll
            for (int i = 0; i < 2; ++i) {
                int q = t + i * 256;
                int k = k0 + (q >> 3);
                const float* src = ((k < HD) ? wi + (size_t)k * ND : wh + (size_t)(k - HD) * ND) + n0;
                v[t2 * 2 + i] = *(const float4*)(src + (q & 7) * 4);
            }
        }
#pragma unroll
        for (int t2 = 0; t2 < 2; ++t2) {
            float (*s)[36] = (float(*)[36])(sm + t2 * 2304);
#pragma unroll
            for (int i = 0; i < 2; ++i) {
                int q = t + i * 256;
                int kr = q >> 3, c4 = q & 7;
                float4 w = v[t2 * 2 + i];
                s[kr][c4 * 4 + 0] = w.x; s[kr][c4 * 4 + 1] = w.y;
                s[kr][c4 * 4 + 2] = w.z; s[kr][c4 * 4 + 3] = w.w;
            }
        }
        __syncthreads();
#pragma unroll
        for (int t2 = 0; t2 < 2; ++t2) {
            float (*s)[36] = (float(*)[36])(sm + t2 * 2304);
#pragma unroll
            for (int i = 0; i < 2; ++i) {
                int u = t + i * 256;
                int w = u >> 7, k16 = (u >> 5) & 3, lane = u & 31;
                int nl = w * 8 + (lane >> 2);
                int kk = k16 * 16 + (lane & 3) * 2;
                __half2 p[2];
                p[0] = __floats2half2_rn(s[kk][nl], s[kk + 1][nl]);
                p[1] = __floats2half2_rn(s[kk + 8][nl], s[kk + 9][nl]);
                int nbp = tt * 16 + w * 4 + gate;
                size_t idx = ((size_t)(nbp * 128 + (kp + t2) * 4 + k16) * 32 + lane) * 4;
                *(uint2*)(g_Bpk + idx) = *(uint2*)p;
            }
        }
    }
}

// ---- fused fp16 GEMM (128x128 tile, 256 thr, 2 CTAs/SM) + LSTM epilogue ----
__global__ void __launch_bounds__(256, 2) gemm_lstm(const float* __restrict__ c_t,
                                                    const float* __restrict__ b_i,
                                                    const float* __restrict__ b_h,
                                                    float* __restrict__ out) {
    extern __shared__ char smem[];
    const uint32_t sb = smem_u32(smem);
    float* bias_s = (float*)(smem + SM_BIAS);
    const int tid = threadIdx.x, wid = tid >> 5, lane = tid & 31;
    const int wm = wid >> 2, wn = wid & 3;         // 2 x 4 warp grid, warp tile 64x32
    const int m0 = blockIdx.y * TM;
    const int bx = blockIdx.x;
    const int mb0 = blockIdx.y * 8, nb0 = bx * 16;

    float acc[4][4][4];
#pragma unroll
    for (int i = 0; i < 4; ++i)
#pragma unroll
        for (int j = 0; j < 4; ++j)
#pragma unroll
            for (int u = 0; u < 4; ++u) acc[i][j][u] = 0.f;

    auto issue = [&](int s, int kc) {
        const uint32_t SA = sb + s * STG_BYTES, SB = SA + STG_A;
#pragma unroll
        for (int i = 0; i < 4; ++i) {
            int u = tid + i * 256;
            int mb = u >> 7, j = (u >> 5) & 3, ln = u & 31;
            cpa16(SA + u * 16,
                  g_Apk + ((size_t)((mb0 + mb) * 128 + kc * 4 + j) * 32 + ln) * 8);
        }
#pragma unroll
        for (int i = 0; i < 4; ++i) {
            int u = tid + i * 256;
            int nb = u >> 6, j = (u >> 4) & 3, q = u & 15;
            cpa16(SB + u * 16,
                  g_Bpk + ((size_t)((nb0 + nb) * 128 + kc * 4 + j) * 32) * 4 + q * 8);
        }
        cpa_commit();
    };

    issue(0, 0);
    issue(1, 1);

    if (tid < 128) {
        int gate = tid >> 5, hl = tid & 31, col = gate * 1024 + bx * 32 + hl;
        bias_s[tid] = b_i[col] + b_h[col];
    }

    const uint32_t aoff = (uint32_t)(wm * 4) * 2048 + lane * 16;        // + im*2048 + j*512
    const uint32_t boff = STG_A + (uint32_t)(wn * 4) * 1024 + lane * 8; // + in*1024 + j*256

    for (int kc = 0; kc < NKC; ++kc) {
        const int s = kc % NSTG;
        cpa_wait<1>();
        __syncthreads();
        const uint32_t SA = sb + s * STG_BYTES;
        const uint32_t ab = SA + aoff, bb = SA + boff;

        uint32_t a[2][4][4], b[2][4][2];
#pragma unroll
        for (int im = 0; im < 4; ++im) LDS128(a[0][im], ab + im * 2048);
#pragma unroll
        for (int in = 0; in < 4; ++in) LDS64(b[0][in], bb + in * 1024);

        if (kc + 2 < NKC) issue((kc + 2) % NSTG, kc + 2);
        else cpa_commit();               // keep group count for wait<1>

#pragma unroll
        for (int j = 0; j < 4; ++j) {
            const int cur = j & 1, nxt = cur ^ 1;
#pragma unroll
            for (int im = 0; im < 4; ++im) {
#pragma unroll
                for (int in = 0; in < 4; ++in)
                    MMA16(acc[im][in], a[cur][im], b[cur][in]);
                if (j < 3) {             // interleave j+1 loads between MMA groups
                    if (im == 0) {
#pragma unroll
                        for (int in = 0; in < 4; ++in)
                            LDS64(b[nxt][in], bb + in * 1024 + (j + 1) * 256);
                    } else if (im == 1) {
                        LDS128(a[nxt][0], ab + (j + 1) * 512);
                        LDS128(a[nxt][1], ab + 2048 + (j + 1) * 512);
                    } else if (im == 2) {
                        LDS128(a[nxt][2], ab + 4096 + (j + 1) * 512);
                        LDS128(a[nxt][3], ab + 6144 + (j + 1) * 512);
                    }
                }
            }
        }
    }

    // ---- fused epilogue: in-index = gate ----
    const int hl = wn * 8 + (lane & 3) * 2;
    const int hc = bx * 32 + hl;
    const int rb = m0 + wm * 64 + (lane >> 2);
    float bI0 = bias_s[hl],      bI1 = bias_s[hl + 1];
    float bF0 = bias_s[32 + hl], bF1 = bias_s[33 + hl];
    float bG0 = bias_s[64 + hl], bG1 = bias_s[65 + hl];
    float bO0 = bias_s[96 + hl], bO1 = bias_s[97 + hl];
#pragma unroll
    for (int im = 0; im < 4; ++im)
#pragma unroll
        for (int half = 0; half < 2; ++half) {
            const int r = rb + im * 16 + half * 8;
            const int q = half * 2;
            float2 cv = *(const float2*)(c_t + (size_t)r * HD + hc);
            float I0 = sigf(acc[im][0][q] + bI0),   I1 = sigf(acc[im][0][q + 1] + bI1);
            float F0 = sigf(acc[im][1][q] + bF0),   F1 = sigf(acc[im][1][q + 1] + bF1);
            float G0 = tanhf_(acc[im][2][q] + bG0), G1 = tanhf_(acc[im][2][q + 1] + bG1);
            float O0 = sigf(acc[im][3][q] + bO0),   O1 = sigf(acc[im][3][q + 1] + bO1);
            float cn0 = F0 * cv.x + I0 * G0,        cn1 = F1 * cv.y + I1 * G1;
            float hn0 = O0 * tanhf_(cn0),           hn1 = O1 * tanhf_(cn1);
            *(float2*)(out + (size_t)r * HD + hc) = make_float2(hn0, hn1);
            *(float2*)(out + (size_t)BD * HD + (size_t)r * HD + hc) = make_float2(cn0, cn1);
        }
}

extern "C" void kernel_launch(void* const* d_in, const int* in_sizes, int n_in,
                              void* d_out, int out_size) {
    const float* input = (const float*)d_in[0];
    const float* h_t   = (const float*)d_in[1];
    const float* c_t   = (const float*)d_in[2];
    const float* w_i   = (const float*)d_in[3];
    const float* w_h   = (const float*)d_in[4];
    const float* b_i   = (const float*)d_in[5];
    const float* b_h   = (const float*)d_in[6];
    float* out = (float*)d_out;

    cudaFuncSetAttribute(gemm_lstm, cudaFuncAttributeMaxDynamicSharedMemorySize, SMEM_TOTAL);

    pack_ab<<<4096, 256>>>(input, h_t, w_i, w_h);
    gemm_lstm<<<dim3(ND / TN, BD / TM), 256, SMEM_TOTAL>>>(c_t, b_i, b_h, out);
}